// round 15
// baseline (speedup 1.0000x reference)
#include <cuda_runtime.h>
#include <cuda_fp16.h>
#include <math.h>
#include <stdint.h>

// ---------------- problem constants ----------------
#define BATCH  512
#define CH     3
#define NIN    1024
#define DICT   2048
#define LAYERS 30
#define NFP16  26                  // 0..25 fp16 (scaled), 26..29 tf32 cleanup
#define TAUV   0.1f
#define LAMV   0.1f

// fp16 exponent scaling: A x 2^8, G x 2^4 -> acc x 2^12 (undone in epilogue)
#define SCL_A   256.0f
#define SCL_G   16.0f
#define INV_SCL (1.0f / 4096.0f)

// ---------------- GEMM tiling (shared geometry) ----------------
#define BM 64
#define BN 128
#define NSTAGE 4
#define A_BYTES (BM * 64)           // 4 KB per stage
#define B_BYTES (BN * 64)           // 8 KB per stage
#define STAGE_BYTES (A_BYTES + B_BYTES)   // 12 KB
#define SMEM_DYN (NSTAGE * STAGE_BYTES)   // 48 KB

// ---------------- scratch (allocation-free) ----------------
__device__ __align__(256) float  g_G [(size_t)CH * DICT * DICT];     // Gram fp32
__device__ __align__(256) __half g_Gh[(size_t)CH * DICT * DICT];     // Gram fp16 (x16)
__device__ __align__(256) float  g_Y [(size_t)CH * BATCH * DICT];
__device__ __align__(256) float  g_Wt[(size_t)CH * NIN * DICT];
__device__ __align__(256) float  g_buf[(size_t)4 * CH * BATCH * DICT];
__device__ __align__(256) __half g_bufh[(size_t)2 * CH * BATCH * DICT]; // fp16 momentum (x256)

// ---------------- helpers ----------------
__device__ __forceinline__ uint32_t smem_u32(const void* p) {
    uint32_t a;
    asm("{ .reg .u64 t; cvta.to.shared.u64 t, %1; cvt.u32.u64 %0, t; }" : "=r"(a) : "l"(p));
    return a;
}
__device__ __forceinline__ uint32_t swz(uint32_t x) { return x ^ ((x >> 3) & 0x30); }

__device__ __forceinline__ void cp16(uint32_t dst, const void* src) {
    asm volatile("cp.async.cg.shared.global [%0], [%1], 16;" :: "r"(dst), "l"(src));
}
#define CP_COMMIT() asm volatile("cp.async.commit_group;" ::: "memory")
#define CP_WAIT(n)  asm volatile("cp.async.wait_group %0;" :: "n"(n) : "memory")

__device__ __forceinline__ void ldmx4(uint32_t r[4], uint32_t addr) {
    asm volatile("ldmatrix.sync.aligned.m8n8.x4.shared.b16 {%0,%1,%2,%3}, [%4];"
                 : "=r"(r[0]), "=r"(r[1]), "=r"(r[2]), "=r"(r[3]) : "r"(addr));
}
__device__ __forceinline__ void mma_tf32(float d[4], const uint32_t a[4], const uint32_t b[2]) {
    asm volatile(
        "mma.sync.aligned.m16n8k8.row.col.f32.tf32.tf32.f32 "
        "{%0,%1,%2,%3}, {%4,%5,%6,%7}, {%8,%9}, {%0,%1,%2,%3};"
        : "+f"(d[0]), "+f"(d[1]), "+f"(d[2]), "+f"(d[3])
        : "r"(a[0]), "r"(a[1]), "r"(a[2]), "r"(a[3]), "r"(b[0]), "r"(b[1]));
}
__device__ __forceinline__ void mma_f16(float d[4], const uint32_t a[4], const uint32_t b[2]) {
    asm volatile(
        "mma.sync.aligned.m16n8k16.row.col.f32.f16.f16.f32 "
        "{%0,%1,%2,%3}, {%4,%5,%6,%7}, {%8,%9}, {%0,%1,%2,%3};"
        : "+f"(d[0]), "+f"(d[1]), "+f"(d[2]), "+f"(d[3])
        : "r"(a[0]), "r"(a[1]), "r"(a[2]), "r"(a[3]), "r"(b[0]), "r"(b[1]));
}

// ---------------------------------------------------------------------------
// tf32 GEMM (R8 geometry): D[M,N] = A[M,K] · B[N,K]^T, both K-major fp32.
// MODE 0: fp32 store.  MODE 1: fused FISTA epilogue (tf32 cleanup iters).
// MODE 3: dual store (fp32 -> C, fp16 x SCL_G -> g_Gh) for the Gram matrix.
// ---------------------------------------------------------------------------
template<int MODE>
__global__ void __launch_bounds__(128, 4)
tgemm(const float* __restrict__ A, long sA, int lda,
      const float* __restrict__ Bm, long sB, int ldb,
      float* __restrict__ C, long sC, int ldc,
      int K,
      const float* __restrict__ Yp,
      const float* __restrict__ Xold,
      float* __restrict__ Xmom,
      float beta)
{
    extern __shared__ char smem[];
    const uint32_t sb = smem_u32(smem);

    const int tid  = threadIdx.x;
    const int lane = tid & 31;
    const int wid  = tid >> 5;
    const int wm   = wid & 1;
    const int wn   = wid >> 1;
    const int lm   = lane >> 3;
    const int lr   = lane & 7;

    const int cz = blockIdx.z;
    const int bm = blockIdx.y * BM;
    const int bn = blockIdx.x * BN;

    const float* Ach = A  + (long)cz * sA;
    const float* Bch = Bm + (long)cz * sB;

    float acc[2][8][4];
#pragma unroll
    for (int i = 0; i < 2; ++i)
#pragma unroll
        for (int j = 0; j < 8; ++j)
#pragma unroll
            for (int k = 0; k < 4; ++k) acc[i][j][k] = 0.f;

    auto load_chunk = [&](int ck, int s) {
        const uint32_t st = sb + s * STAGE_BYTES;
        const long kof = (long)ck * 16;
#pragma unroll
        for (int i = 0; i < 2; ++i) {
            int f = tid + i * 128;
            int row = f >> 2, c = f & 3;
            cp16(st + swz(row * 64 + c * 16),
                 Ach + (long)(bm + row) * lda + kof + c * 4);
        }
#pragma unroll
        for (int i = 0; i < 4; ++i) {
            int f = tid + i * 128;
            int row = f >> 2, c = f & 3;
            cp16(st + A_BYTES + swz(row * 64 + c * 16),
                 Bch + (long)(bn + row) * ldb + kof + c * 4);
        }
    };

    const int NK = K / 16;
#pragma unroll
    for (int s = 0; s < NSTAGE - 1; ++s) { load_chunk(s, s); CP_COMMIT(); }

    const int aRow = (lm & 1) * 8 + lr;
    const int aChk = lm >> 1;
    const int bNt  = lm >> 1;
    const int bChk = lm & 1;

#pragma unroll 1
    for (int ck = 0; ck < NK; ++ck) {
        CP_WAIT(2);
        __syncthreads();
        const int cn = ck + NSTAGE - 1;
        if (cn < NK) load_chunk(cn, cn & (NSTAGE - 1));
        CP_COMMIT();

        const uint32_t st = sb + (ck & (NSTAGE - 1)) * STAGE_BYTES;
#pragma unroll
        for (int ks = 0; ks < 2; ++ks) {
            uint32_t a[2][4], b[8][2];
#pragma unroll
            for (int mi = 0; mi < 2; ++mi) {
                int row = wm * 32 + mi * 16 + aRow;
                int ch  = ks * 2 + aChk;
                ldmx4(a[mi], st + swz(row * 64 + ch * 16));
            }
#pragma unroll
            for (int p = 0; p < 4; ++p) {
                int nt  = p * 2 + bNt;
                int ch  = ks * 2 + bChk;
                int row = wn * 64 + nt * 8 + lr;
                uint32_t r[4];
                ldmx4(r, st + A_BYTES + swz(row * 64 + ch * 16));
                b[p * 2][0] = r[0]; b[p * 2][1] = r[1];
                b[p * 2 + 1][0] = r[2]; b[p * 2 + 1][1] = r[3];
            }
#pragma unroll
            for (int mi = 0; mi < 2; ++mi)
#pragma unroll
                for (int ni = 0; ni < 8; ++ni)
                    mma_tf32(acc[mi][ni], a[mi], b[ni]);
        }
    }

    const int qr = lane >> 2;
    const int qc = lane & 3;

    if (MODE == 0 || MODE == 3) {
        float* Cch = C + (long)cz * sC;
#pragma unroll
        for (int mi = 0; mi < 2; ++mi) {
            const int r0 = bm + wm * 32 + mi * 16 + qr;
#pragma unroll
            for (int ni = 0; ni < 8; ++ni) {
                const int col = bn + wn * 64 + ni * 8 + qc * 2;
                float* p0 = Cch + (long)r0 * ldc + col;
                float* p1 = p0 + 8L * ldc;
                *(float2*)p0 = make_float2(acc[mi][ni][0], acc[mi][ni][1]);
                *(float2*)p1 = make_float2(acc[mi][ni][2], acc[mi][ni][3]);
                if (MODE == 3) {
                    __half* h0 = g_Gh + (long)cz * sC + (long)r0 * ldc + col;
                    __half* h1 = h0 + 8L * ldc;
                    *(__half2*)h0 = __floats2half2_rn(acc[mi][ni][0] * SCL_G,
                                                      acc[mi][ni][1] * SCL_G);
                    *(__half2*)h1 = __floats2half2_rn(acc[mi][ni][2] * SCL_G,
                                                      acc[mi][ni][3] * SCL_G);
                }
            }
        }
    } else {
        // MODE 1: fused FISTA epilogue (tf32 cleanup iterations)
        const float* Ych = Yp   + (long)cz * sC;
        const float* Och = Xold + (long)cz * sC;
        float*       Mch = Xmom + (long)cz * sC;
        float*       Cch = C    + (long)cz * sC;
#pragma unroll
        for (int mi = 0; mi < 2; ++mi) {
            const int r0 = bm + wm * 32 + mi * 16 + qr;
#pragma unroll
            for (int ni = 0; ni < 8; ++ni) {
                const int col = bn + wn * 64 + ni * 8 + qc * 2;
                const long off0 = (long)r0 * ldc + col;
                const long off1 = off0 + 8L * ldc;
                const float2 xt0 = *(const float2*)(Ach + (long)r0 * lda + col);
                const float2 xt1 = *(const float2*)(Ach + (long)(r0 + 8) * lda + col);
                const float2 y0  = *(const float2*)(Ych + off0);
                const float2 y1  = *(const float2*)(Ych + off1);
                float v00 = xt0.x + TAUV * (y0.x - acc[mi][ni][0]);
                float v01 = xt0.y + TAUV * (y0.y - acc[mi][ni][1]);
                float v10 = xt1.x + TAUV * (y1.x - acc[mi][ni][2]);
                float v11 = xt1.y + TAUV * (y1.y - acc[mi][ni][3]);
                float ss0 = fmaf(v00, v00, v01 * v01);
                float ss1 = fmaf(v10, v10, v11 * v11);
                ss0 += __shfl_xor_sync(0xffffffffu, ss0, 1);
                ss1 += __shfl_xor_sync(0xffffffffu, ss1, 1);
                ss0 += __shfl_xor_sync(0xffffffffu, ss0, 2);
                ss1 += __shfl_xor_sync(0xffffffffu, ss1, 2);
                const float sc0 = fmaxf(1.f - (LAMV * TAUV) * rsqrtf(ss0), 0.f);
                const float sc1 = fmaxf(1.f - (LAMV * TAUV) * rsqrtf(ss1), 0.f);
                const float2 xo0 = *(const float2*)(Och + off0);
                const float2 xo1 = *(const float2*)(Och + off1);
                float xn00 = sc0 * fmaxf(v00, 0.f);
                float xn01 = sc0 * fmaxf(v01, 0.f);
                float xn10 = sc1 * fmaxf(v10, 0.f);
                float xn11 = sc1 * fmaxf(v11, 0.f);
                *(float2*)(Cch + off0) = make_float2(xn00, xn01);
                *(float2*)(Cch + off1) = make_float2(xn10, xn11);
                *(float2*)(Mch + off0) = make_float2(
                    xn00 + beta * (xn00 - xo0.x), xn01 + beta * (xn01 - xo0.y));
                *(float2*)(Mch + off1) = make_float2(
                    xn10 + beta * (xn10 - xo1.x), xn11 + beta * (xn11 - xo1.y));
            }
        }
    }
}

// ---------------------------------------------------------------------------
// fp16 iter GEMM + fused FISTA epilogue (iterations 0..NFP16-1).
// Operands exponent-scaled (A x256, G x16); accumulator x4096 undone here.
// FISTA state fp32; writes scaled fp16 momentum for the next fp16 iter.
// ---------------------------------------------------------------------------
__global__ void __launch_bounds__(128, 4)
hgemm_fista(const __half* __restrict__ Ah,
            const float*  __restrict__ Af,
            const __half* __restrict__ Bh,
            float* __restrict__ Cn,
            const float* __restrict__ Yp,
            const float* __restrict__ Xold,
            float* __restrict__ Xm32,
            __half* __restrict__ XmH,
            float beta)
{
    extern __shared__ char smem[];
    const uint32_t sb = smem_u32(smem);

    const int tid  = threadIdx.x;
    const int lane = tid & 31;
    const int wid  = tid >> 5;
    const int wm   = wid & 1;
    const int wn   = wid >> 1;
    const int lm   = lane >> 3;
    const int lr   = lane & 7;

    const int cz = blockIdx.z;
    const int bm = blockIdx.y * BM;
    const int bn = blockIdx.x * BN;

    const long slab = (long)BATCH * DICT;
    const __half* Ach = Ah + (long)cz * slab;
    const __half* Bch = Bh + (long)cz * DICT * DICT;

    float acc[2][8][4];
#pragma unroll
    for (int i = 0; i < 2; ++i)
#pragma unroll
        for (int j = 0; j < 8; ++j)
#pragma unroll
            for (int k = 0; k < 4; ++k) acc[i][j][k] = 0.f;

    auto load_chunk = [&](int ck, int s) {
        const uint32_t st = sb + s * STAGE_BYTES;
        const long kof = (long)ck * 32;
#pragma unroll
        for (int i = 0; i < 2; ++i) {
            int f = tid + i * 128;
            int row = f >> 2, c = f & 3;
            cp16(st + swz(row * 64 + c * 16),
                 Ach + (long)(bm + row) * DICT + kof + c * 8);
        }
#pragma unroll
        for (int i = 0; i < 4; ++i) {
            int f = tid + i * 128;
            int row = f >> 2, c = f & 3;
            cp16(st + A_BYTES + swz(row * 64 + c * 16),
                 Bch + (long)(bn + row) * DICT + kof + c * 8);
        }
    };

    const int NK = DICT / 32;
#pragma unroll
    for (int s = 0; s < NSTAGE - 1; ++s) { load_chunk(s, s); CP_COMMIT(); }

    const int aRow = (lm & 1) * 8 + lr;
    const int aChk = lm >> 1;
    const int bNt  = lm >> 1;
    const int bChk = lm & 1;

#pragma unroll 1
    for (int ck = 0; ck < NK; ++ck) {
        CP_WAIT(2);
        __syncthreads();
        const int cn = ck + NSTAGE - 1;
        if (cn < NK) load_chunk(cn, cn & (NSTAGE - 1));
        CP_COMMIT();

        const uint32_t st = sb + (ck & (NSTAGE - 1)) * STAGE_BYTES;
#pragma unroll
        for (int ks = 0; ks < 2; ++ks) {
            uint32_t a[2][4], b[8][2];
#pragma unroll
            for (int mi = 0; mi < 2; ++mi) {
                int row = wm * 32 + mi * 16 + aRow;
                int ch  = ks * 2 + aChk;
                ldmx4(a[mi], st + swz(row * 64 + ch * 16));
            }
#pragma unroll
            for (int p = 0; p < 4; ++p) {
                int nt  = p * 2 + bNt;
                int ch  = ks * 2 + bChk;
                int row = wn * 64 + nt * 8 + lr;
                uint32_t r[4];
                ldmx4(r, st + A_BYTES + swz(row * 64 + ch * 16));
                b[p * 2][0] = r[0]; b[p * 2][1] = r[1];
                b[p * 2 + 1][0] = r[2]; b[p * 2 + 1][1] = r[3];
            }
#pragma unroll
            for (int mi = 0; mi < 2; ++mi)
#pragma unroll
                for (int ni = 0; ni < 8; ++ni)
                    mma_f16(acc[mi][ni], a[mi], b[ni]);
        }
    }

    const int qr = lane >> 2;
    const int qc = lane & 3;
    const float* Afc = Af   + (long)cz * slab;
    const float* Ych = Yp   + (long)cz * slab;
    const float* Och = Xold + (long)cz * slab;
    float*       Mch = Xm32 + (long)cz * slab;
    __half*      Hch = XmH  + (long)cz * slab;
    float*       Cch = Cn   + (long)cz * slab;

#pragma unroll
    for (int mi = 0; mi < 2; ++mi) {
        const int r0 = bm + wm * 32 + mi * 16 + qr;
#pragma unroll
        for (int ni = 0; ni < 8; ++ni) {
            const int col = bn + wn * 64 + ni * 8 + qc * 2;
            const long off0 = (long)r0 * DICT + col;
            const long off1 = off0 + 8L * DICT;
            const float2 xt0 = *(const float2*)(Afc + off0);
            const float2 xt1 = *(const float2*)(Afc + off1);
            const float2 y0  = *(const float2*)(Ych + off0);
            const float2 y1  = *(const float2*)(Ych + off1);
            float v00 = xt0.x + TAUV * (y0.x - acc[mi][ni][0] * INV_SCL);
            float v01 = xt0.y + TAUV * (y0.y - acc[mi][ni][1] * INV_SCL);
            float v10 = xt1.x + TAUV * (y1.x - acc[mi][ni][2] * INV_SCL);
            float v11 = xt1.y + TAUV * (y1.y - acc[mi][ni][3] * INV_SCL);
            float ss0 = fmaf(v00, v00, v01 * v01);
            float ss1 = fmaf(v10, v10, v11 * v11);
            ss0 += __shfl_xor_sync(0xffffffffu, ss0, 1);
            ss1 += __shfl_xor_sync(0xffffffffu, ss1, 1);
            ss0 += __shfl_xor_sync(0xffffffffu, ss0, 2);
            ss1 += __shfl_xor_sync(0xffffffffu, ss1, 2);
            const float sc0 = fmaxf(1.f - (LAMV * TAUV) * rsqrtf(ss0), 0.f);
            const float sc1 = fmaxf(1.f - (LAMV * TAUV) * rsqrtf(ss1), 0.f);
            const float2 xo0 = *(const float2*)(Och + off0);
            const float2 xo1 = *(const float2*)(Och + off1);
            float xn00 = sc0 * fmaxf(v00, 0.f);
            float xn01 = sc0 * fmaxf(v01, 0.f);
            float xn10 = sc1 * fmaxf(v10, 0.f);
            float xn11 = sc1 * fmaxf(v11, 0.f);
            float xm00 = xn00 + beta * (xn00 - xo0.x);
            float xm01 = xn01 + beta * (xn01 - xo0.y);
            float xm10 = xn10 + beta * (xn10 - xo1.x);
            float xm11 = xn11 + beta * (xn11 - xo1.y);
            *(float2*)(Cch + off0) = make_float2(xn00, xn01);
            *(float2*)(Cch + off1) = make_float2(xn10, xn11);
            *(float2*)(Mch + off0) = make_float2(xm00, xm01);
            *(float2*)(Mch + off1) = make_float2(xm10, xm11);
            *(__half2*)(Hch + off0) = __floats2half2_rn(xm00 * SCL_A, xm01 * SCL_A);
            *(__half2*)(Hch + off1) = __floats2half2_rn(xm10 * SCL_A, xm11 * SCL_A);
        }
    }
}

// W [C,D,N] -> Wt [C,N,D] (decoder reuses the A·B^T kernel)
__global__ void transpose_w(const float* __restrict__ W, float* __restrict__ Wt)
{
    __shared__ float tile[32][33];
    const int cz = blockIdx.z;
    const int d0 = blockIdx.x * 32;
    const int n0 = blockIdx.y * 32;
    const float* Wc  = W  + (long)cz * DICT * NIN;
    float*       Wtc = Wt + (long)cz * NIN * DICT;
    const int tx = threadIdx.x, ty = threadIdx.y;
#pragma unroll
    for (int r = 0; r < 32; r += 8)
        tile[ty + r][tx] = Wc[(long)(d0 + ty + r) * NIN + n0 + tx];
    __syncthreads();
#pragma unroll
    for (int r = 0; r < 32; r += 8)
        Wtc[(long)(n0 + ty + r) * DICT + d0 + tx] = tile[tx][ty + r];
}

extern "C" void kernel_launch(void* const* d_in, const int* in_sizes, int n_in,
                              void* d_out, int out_size)
{
    const float* x;
    const float* W;
    if (in_sizes[0] == BATCH * CH * NIN) { x = (const float*)d_in[0]; W = (const float*)d_in[1]; }
    else                                 { x = (const float*)d_in[1]; W = (const float*)d_in[0]; }

    __half *Gh, *bufh;
    float *G, *Y, *Wt, *buf;
    cudaGetSymbolAddress((void**)&G,    g_G);
    cudaGetSymbolAddress((void**)&Gh,   g_Gh);
    cudaGetSymbolAddress((void**)&Y,    g_Y);
    cudaGetSymbolAddress((void**)&Wt,   g_Wt);
    cudaGetSymbolAddress((void**)&buf,  g_buf);
    cudaGetSymbolAddress((void**)&bufh, g_bufh);
    const long slab = (long)CH * BATCH * DICT;

    cudaFuncSetAttribute(tgemm<0>,    cudaFuncAttributeMaxDynamicSharedMemorySize, SMEM_DYN);
    cudaFuncSetAttribute(tgemm<1>,    cudaFuncAttributeMaxDynamicSharedMemorySize, SMEM_DYN);
    cudaFuncSetAttribute(tgemm<3>,    cudaFuncAttributeMaxDynamicSharedMemorySize, SMEM_DYN);
    cudaFuncSetAttribute(hgemm_fista, cudaFuncAttributeMaxDynamicSharedMemorySize, SMEM_DYN);

    float betas[LAYERS];
    float tt = 1.f;
    for (int i = 0; i < LAYERS; ++i) {
        float tn = (1.f + sqrtf(1.f + 4.f * tt * tt)) * 0.5f;
        betas[i] = (tt - 1.f) / tn;
        tt = tn;
    }

    cudaMemsetAsync(buf,  0, (size_t)2 * slab * sizeof(float));
    cudaMemsetAsync(bufh, 0, (size_t)slab * sizeof(__half));

    // Gram: G_c = W_c · W_c^T -> fp32 + fp16(x16)  [2048 x 2048, K=1024]
    tgemm<3><<<dim3(DICT / BN, DICT / BM, CH), 128, SMEM_DYN>>>(
        W, (long)DICT * NIN, NIN,
        W, (long)DICT * NIN, NIN,
        G, (long)DICT * DICT, DICT,
        NIN, nullptr, nullptr, nullptr, 0.f);

    // Y_c = x_c · W_c^T (fp32)  [512 x 2048, K=1024]
    tgemm<0><<<dim3(DICT / BN, BATCH / BM, CH), 128, SMEM_DYN>>>(
        x, (long)NIN, CH * NIN,
        W, (long)DICT * NIN, NIN,
        Y, (long)BATCH * DICT, DICT,
        NIN, nullptr, nullptr, nullptr, 0.f);

    transpose_w<<<dim3(DICT / 32, NIN / 32, CH), dim3(32, 8)>>>(W, Wt);

    // FISTA: iterations 0..NFP16-1 scaled-fp16, NFP16..29 tf32 cleanup
    for (int i = 0; i < LAYERS; ++i) {
        const int odd = i & 1;
        float*  oldb = buf  + (odd ? 2 : 0) * slab;
        float*  tmpb = buf  + (odd ? 3 : 1) * slab;
        float*  newb = buf  + (odd ? 0 : 2) * slab;
        float*  momb = buf  + (odd ? 1 : 3) * slab;
        __half* tmph = bufh + (odd ? 1 : 0) * slab;
        __half* momh = bufh + (odd ? 0 : 1) * slab;
        if (i < NFP16) {
            hgemm_fista<<<dim3(DICT / BN, BATCH / BM, CH), 128, SMEM_DYN>>>(
                tmph, tmpb, Gh, newb, Y, oldb, momb, momh, betas[i]);
        } else {
            tgemm<1><<<dim3(DICT / BN, BATCH / BM, CH), 128, SMEM_DYN>>>(
                tmpb, (long)BATCH * DICT, DICT,
                G,    (long)DICT * DICT, DICT,
                newb, (long)BATCH * DICT, DICT,
                DICT, Y, oldb, momb, betas[i]);
        }
    }

    float* z = buf;   // x_new after iter 29 (odd) is slab 0

    // Decoder: x_hat_c = z_c · W_c (tf32) -> d_out [B,C,N]
    tgemm<0><<<dim3(NIN / BN, BATCH / BM, CH), 128, SMEM_DYN>>>(
        z,  (long)BATCH * DICT, DICT,
        Wt, (long)NIN * DICT, DICT,
        (float*)d_out, (long)NIN, CH * NIN,
        DICT, nullptr, nullptr, nullptr, 0.f);
}

// round 16
// speedup vs baseline: 1.4975x; 1.4975x over previous
#include <cuda_runtime.h>
#include <cuda_fp16.h>
#include <math.h>
#include <stdint.h>

// ---------------- problem constants ----------------
#define BATCH  512
#define CH     3
#define NIN    1024
#define DICT   2048
#define LAYERS 30
#define NFP16  22                  // 0..21 fp16 iters, 22..29 tf32 cleanup
#define TAUV   0.1f
#define LAMV   0.1f

// ---------------- GEMM tiling (shared geometry) ----------------
#define BM 64
#define BN 128
#define NSTAGE 4
#define A_BYTES (BM * 64)           // 4 KB per stage
#define B_BYTES (BN * 64)           // 8 KB per stage
#define STAGE_BYTES (A_BYTES + B_BYTES)   // 12 KB
#define SMEM_DYN (NSTAGE * STAGE_BYTES)   // 48 KB

// ---------------- scratch (allocation-free) ----------------
__device__ __align__(256) float  g_G  [(size_t)CH * DICT * DICT];   // Gram fp32 (cleanup iters)
__device__ __align__(256) __half g_Gh [(size_t)CH * DICT * DICT];   // Gram fp16 (fp16 iters)
__device__ __align__(256) float  g_Y  [(size_t)CH * BATCH * DICT];
__device__ __align__(256) __half g_Wh [(size_t)CH * DICT * NIN];    // W fp16 [C,D,N]
__device__ __align__(256) __half g_Wth[(size_t)CH * NIN * DICT];    // W^T fp16 [C,N,D]
__device__ __align__(256) __half g_xh [(size_t)BATCH * CH * NIN];   // x fp16
__device__ __align__(256) __half g_zh [(size_t)CH * BATCH * DICT];  // z fp16 (decoder A)
__device__ __align__(256) float  g_buf[(size_t)4 * CH * BATCH * DICT];
__device__ __align__(256) __half g_bufh[(size_t)2 * CH * BATCH * DICT];

// ---------------- helpers ----------------
__device__ __forceinline__ uint32_t smem_u32(const void* p) {
    uint32_t a;
    asm("{ .reg .u64 t; cvta.to.shared.u64 t, %1; cvt.u32.u64 %0, t; }" : "=r"(a) : "l"(p));
    return a;
}
__device__ __forceinline__ uint32_t swz(uint32_t x) { return x ^ ((x >> 3) & 0x30); }

__device__ __forceinline__ void cp16(uint32_t dst, const void* src) {
    asm volatile("cp.async.cg.shared.global [%0], [%1], 16;" :: "r"(dst), "l"(src));
}
#define CP_COMMIT() asm volatile("cp.async.commit_group;" ::: "memory")
#define CP_WAIT(n)  asm volatile("cp.async.wait_group %0;" :: "n"(n) : "memory")

__device__ __forceinline__ void ldmx4(uint32_t r[4], uint32_t addr) {
    asm volatile("ldmatrix.sync.aligned.m8n8.x4.shared.b16 {%0,%1,%2,%3}, [%4];"
                 : "=r"(r[0]), "=r"(r[1]), "=r"(r[2]), "=r"(r[3]) : "r"(addr));
}
__device__ __forceinline__ void mma_tf32(float d[4], const uint32_t a[4], const uint32_t b[2]) {
    asm volatile(
        "mma.sync.aligned.m16n8k8.row.col.f32.tf32.tf32.f32 "
        "{%0,%1,%2,%3}, {%4,%5,%6,%7}, {%8,%9}, {%0,%1,%2,%3};"
        : "+f"(d[0]), "+f"(d[1]), "+f"(d[2]), "+f"(d[3])
        : "r"(a[0]), "r"(a[1]), "r"(a[2]), "r"(a[3]), "r"(b[0]), "r"(b[1]));
}
__device__ __forceinline__ void mma_f16(float d[4], const uint32_t a[4], const uint32_t b[2]) {
    asm volatile(
        "mma.sync.aligned.m16n8k16.row.col.f32.f16.f16.f32 "
        "{%0,%1,%2,%3}, {%4,%5,%6,%7}, {%8,%9}, {%0,%1,%2,%3};"
        : "+f"(d[0]), "+f"(d[1]), "+f"(d[2]), "+f"(d[3])
        : "r"(a[0]), "r"(a[1]), "r"(a[2]), "r"(a[3]), "r"(b[0]), "r"(b[1]));
}

// ---------------------------------------------------------------------------
// Generic fp16 GEMM: D[M,N] = A[M,K] · B[N,K]^T (A,B fp16 K-major, fp32 acc).
// BK = 32 halfs (64B rows). MODE 0: fp32 store. MODE 3: fp32 + fp16 -> g_Gh.
// ---------------------------------------------------------------------------
template<int MODE>
__global__ void __launch_bounds__(128, 4)
hgemm(const __half* __restrict__ A, long sA, int lda,
      const __half* __restrict__ Bm, long sB, int ldb,
      float* __restrict__ C, long sC, int ldc, int K)
{
    extern __shared__ char smem[];
    const uint32_t sb = smem_u32(smem);

    const int tid  = threadIdx.x;
    const int lane = tid & 31;
    const int wid  = tid >> 5;
    const int wm   = wid & 1;
    const int wn   = wid >> 1;
    const int lm   = lane >> 3;
    const int lr   = lane & 7;

    const int cz = blockIdx.z;
    const int bm = blockIdx.y * BM;
    const int bn = blockIdx.x * BN;

    const __half* Ach = A  + (long)cz * sA;
    const __half* Bch = Bm + (long)cz * sB;

    float acc[2][8][4];
#pragma unroll
    for (int i = 0; i < 2; ++i)
#pragma unroll
        for (int j = 0; j < 8; ++j)
#pragma unroll
            for (int k = 0; k < 4; ++k) acc[i][j][k] = 0.f;

    auto load_chunk = [&](int ck, int s) {
        const uint32_t st = sb + s * STAGE_BYTES;
        const long kof = (long)ck * 32;
#pragma unroll
        for (int i = 0; i < 2; ++i) {
            int f = tid + i * 128;
            int row = f >> 2, c = f & 3;
            cp16(st + swz(row * 64 + c * 16),
                 Ach + (long)(bm + row) * lda + kof + c * 8);
        }
#pragma unroll
        for (int i = 0; i < 4; ++i) {
            int f = tid + i * 128;
            int row = f >> 2, c = f & 3;
            cp16(st + A_BYTES + swz(row * 64 + c * 16),
                 Bch + (long)(bn + row) * ldb + kof + c * 8);
        }
    };

    const int NK = K / 32;
#pragma unroll
    for (int s = 0; s < NSTAGE - 1; ++s) { load_chunk(s, s); CP_COMMIT(); }

    const int aRow = (lm & 1) * 8 + lr;
    const int aChk = lm >> 1;
    const int bNt  = lm >> 1;
    const int bChk = lm & 1;

#pragma unroll 1
    for (int ck = 0; ck < NK; ++ck) {
        CP_WAIT(2);
        __syncthreads();
        const int cn = ck + NSTAGE - 1;
        if (cn < NK) load_chunk(cn, cn & (NSTAGE - 1));
        CP_COMMIT();

        const uint32_t st = sb + (ck & (NSTAGE - 1)) * STAGE_BYTES;
#pragma unroll
        for (int ks = 0; ks < 2; ++ks) {
            uint32_t a[2][4], b[8][2];
#pragma unroll
            for (int mi = 0; mi < 2; ++mi) {
                int row = wm * 32 + mi * 16 + aRow;
                int ch  = ks * 2 + aChk;
                ldmx4(a[mi], st + swz(row * 64 + ch * 16));
            }
#pragma unroll
            for (int p = 0; p < 4; ++p) {
                int nt  = p * 2 + bNt;
                int ch  = ks * 2 + bChk;
                int row = wn * 64 + nt * 8 + lr;
                uint32_t r[4];
                ldmx4(r, st + A_BYTES + swz(row * 64 + ch * 16));
                b[p * 2][0] = r[0]; b[p * 2][1] = r[1];
                b[p * 2 + 1][0] = r[2]; b[p * 2 + 1][1] = r[3];
            }
#pragma unroll
            for (int mi = 0; mi < 2; ++mi)
#pragma unroll
                for (int ni = 0; ni < 8; ++ni)
                    mma_f16(acc[mi][ni], a[mi], b[ni]);
        }
    }

    const int qr = lane >> 2;
    const int qc = lane & 3;
    float* Cch = C + (long)cz * sC;
#pragma unroll
    for (int mi = 0; mi < 2; ++mi) {
        const int r0 = bm + wm * 32 + mi * 16 + qr;
#pragma unroll
        for (int ni = 0; ni < 8; ++ni) {
            const int col = bn + wn * 64 + ni * 8 + qc * 2;
            float* p0 = Cch + (long)r0 * ldc + col;
            float* p1 = p0 + 8L * ldc;
            *(float2*)p0 = make_float2(acc[mi][ni][0], acc[mi][ni][1]);
            *(float2*)p1 = make_float2(acc[mi][ni][2], acc[mi][ni][3]);
            if (MODE == 3) {
                __half* h0 = g_Gh + (long)cz * sC + (long)r0 * ldc + col;
                __half* h1 = h0 + 8L * ldc;
                *(__half2*)h0 = __floats2half2_rn(acc[mi][ni][0], acc[mi][ni][1]);
                *(__half2*)h1 = __floats2half2_rn(acc[mi][ni][2], acc[mi][ni][3]);
            }
        }
    }
}

// ---------------------------------------------------------------------------
// tf32 iter GEMM + fused FISTA epilogue (cleanup iterations; hardcoded DICT).
// ---------------------------------------------------------------------------
__global__ void __launch_bounds__(128, 4)
tgemm_fista(const float* __restrict__ A,
            const float* __restrict__ Bm,
            float* __restrict__ C,
            const float* __restrict__ Yp,
            const float* __restrict__ Xold,
            float* __restrict__ Xmom,
            float beta)
{
    extern __shared__ char smem[];
    const uint32_t sb = smem_u32(smem);

    const int tid  = threadIdx.x;
    const int lane = tid & 31;
    const int wid  = tid >> 5;
    const int wm   = wid & 1;
    const int wn   = wid >> 1;
    const int lm   = lane >> 3;
    const int lr   = lane & 7;

    const int cz = blockIdx.z;
    const int bm = blockIdx.y * BM;
    const int bn = blockIdx.x * BN;

    const long slab = (long)BATCH * DICT;
    const float* Ach = A  + (long)cz * slab;
    const float* Bch = Bm + (long)cz * DICT * DICT;

    float acc[2][8][4];
#pragma unroll
    for (int i = 0; i < 2; ++i)
#pragma unroll
        for (int j = 0; j < 8; ++j)
#pragma unroll
            for (int k = 0; k < 4; ++k) acc[i][j][k] = 0.f;

    auto load_chunk = [&](int ck, int s) {
        const uint32_t st = sb + s * STAGE_BYTES;
        const long kof = (long)ck * 16;
#pragma unroll
        for (int i = 0; i < 2; ++i) {
            int f = tid + i * 128;
            int row = f >> 2, c = f & 3;
            cp16(st + swz(row * 64 + c * 16),
                 Ach + (long)(bm + row) * DICT + kof + c * 4);
        }
#pragma unroll
        for (int i = 0; i < 4; ++i) {
            int f = tid + i * 128;
            int row = f >> 2, c = f & 3;
            cp16(st + A_BYTES + swz(row * 64 + c * 16),
                 Bch + (long)(bn + row) * DICT + kof + c * 4);
        }
    };

    const int NK = DICT / 16;
#pragma unroll
    for (int s = 0; s < NSTAGE - 1; ++s) { load_chunk(s, s); CP_COMMIT(); }

    const int aRow = (lm & 1) * 8 + lr;
    const int aChk = lm >> 1;
    const int bNt  = lm >> 1;
    const int bChk = lm & 1;

#pragma unroll 1
    for (int ck = 0; ck < NK; ++ck) {
        CP_WAIT(2);
        __syncthreads();
        const int cn = ck + NSTAGE - 1;
        if (cn < NK) load_chunk(cn, cn & (NSTAGE - 1));
        CP_COMMIT();

        const uint32_t st = sb + (ck & (NSTAGE - 1)) * STAGE_BYTES;
#pragma unroll
        for (int ks = 0; ks < 2; ++ks) {
            uint32_t a[2][4], b[8][2];
#pragma unroll
            for (int mi = 0; mi < 2; ++mi) {
                int row = wm * 32 + mi * 16 + aRow;
                int ch  = ks * 2 + aChk;
                ldmx4(a[mi], st + swz(row * 64 + ch * 16));
            }
#pragma unroll
            for (int p = 0; p < 4; ++p) {
                int nt  = p * 2 + bNt;
                int ch  = ks * 2 + bChk;
                int row = wn * 64 + nt * 8 + lr;
                uint32_t r[4];
                ldmx4(r, st + A_BYTES + swz(row * 64 + ch * 16));
                b[p * 2][0] = r[0]; b[p * 2][1] = r[1];
                b[p * 2 + 1][0] = r[2]; b[p * 2 + 1][1] = r[3];
            }
#pragma unroll
            for (int mi = 0; mi < 2; ++mi)
#pragma unroll
                for (int ni = 0; ni < 8; ++ni)
                    mma_tf32(acc[mi][ni], a[mi], b[ni]);
        }
    }

    const int qr = lane >> 2;
    const int qc = lane & 3;
    const float* Ych = Yp   + (long)cz * slab;
    const float* Och = Xold + (long)cz * slab;
    float*       Mch = Xmom + (long)cz * slab;
    float*       Cch = C    + (long)cz * slab;
#pragma unroll
    for (int mi = 0; mi < 2; ++mi) {
        const int r0 = bm + wm * 32 + mi * 16 + qr;
#pragma unroll
        for (int ni = 0; ni < 8; ++ni) {
            const int col = bn + wn * 64 + ni * 8 + qc * 2;
            const long off0 = (long)r0 * DICT + col;
            const long off1 = off0 + 8L * DICT;
            const float2 xt0 = *(const float2*)(Ach + off0);
            const float2 xt1 = *(const float2*)(Ach + off1);
            const float2 y0  = *(const float2*)(Ych + off0);
            const float2 y1  = *(const float2*)(Ych + off1);
            float v00 = xt0.x + TAUV * (y0.x - acc[mi][ni][0]);
            float v01 = xt0.y + TAUV * (y0.y - acc[mi][ni][1]);
            float v10 = xt1.x + TAUV * (y1.x - acc[mi][ni][2]);
            float v11 = xt1.y + TAUV * (y1.y - acc[mi][ni][3]);
            float ss0 = fmaf(v00, v00, v01 * v01);
            float ss1 = fmaf(v10, v10, v11 * v11);
            ss0 += __shfl_xor_sync(0xffffffffu, ss0, 1);
            ss1 += __shfl_xor_sync(0xffffffffu, ss1, 1);
            ss0 += __shfl_xor_sync(0xffffffffu, ss0, 2);
            ss1 += __shfl_xor_sync(0xffffffffu, ss1, 2);
            const float sc0 = fmaxf(1.f - (LAMV * TAUV) * rsqrtf(ss0), 0.f);
            const float sc1 = fmaxf(1.f - (LAMV * TAUV) * rsqrtf(ss1), 0.f);
            const float2 xo0 = *(const float2*)(Och + off0);
            const float2 xo1 = *(const float2*)(Och + off1);
            float xn00 = sc0 * fmaxf(v00, 0.f);
            float xn01 = sc0 * fmaxf(v01, 0.f);
            float xn10 = sc1 * fmaxf(v10, 0.f);
            float xn11 = sc1 * fmaxf(v11, 0.f);
            *(float2*)(Cch + off0) = make_float2(xn00, xn01);
            *(float2*)(Cch + off1) = make_float2(xn10, xn11);
            *(float2*)(Mch + off0) = make_float2(
                xn00 + beta * (xn00 - xo0.x), xn01 + beta * (xn01 - xo0.y));
            *(float2*)(Mch + off1) = make_float2(
                xn10 + beta * (xn10 - xo1.x), xn11 + beta * (xn11 - xo1.y));
        }
    }
}

// ---------------------------------------------------------------------------
// fp16 iter GEMM + fused FISTA epilogue (R14 verbatim, unscaled).
// ---------------------------------------------------------------------------
__global__ void __launch_bounds__(128, 4)
hgemm_fista(const __half* __restrict__ Ah,
            const float*  __restrict__ Af,
            const __half* __restrict__ Bh,
            float* __restrict__ Cn,
            const float* __restrict__ Yp,
            const float* __restrict__ Xold,
            float* __restrict__ Xm32,
            __half* __restrict__ XmH,
            float beta)
{
    extern __shared__ char smem[];
    const uint32_t sb = smem_u32(smem);

    const int tid  = threadIdx.x;
    const int lane = tid & 31;
    const int wid  = tid >> 5;
    const int wm   = wid & 1;
    const int wn   = wid >> 1;
    const int lm   = lane >> 3;
    const int lr   = lane & 7;

    const int cz = blockIdx.z;
    const int bm = blockIdx.y * BM;
    const int bn = blockIdx.x * BN;

    const long slab = (long)BATCH * DICT;
    const __half* Ach = Ah + (long)cz * slab;
    const __half* Bch = Bh + (long)cz * DICT * DICT;

    float acc[2][8][4];
#pragma unroll
    for (int i = 0; i < 2; ++i)
#pragma unroll
        for (int j = 0; j < 8; ++j)
#pragma unroll
            for (int k = 0; k < 4; ++k) acc[i][j][k] = 0.f;

    auto load_chunk = [&](int ck, int s) {
        const uint32_t st = sb + s * STAGE_BYTES;
        const long kof = (long)ck * 32;
#pragma unroll
        for (int i = 0; i < 2; ++i) {
            int f = tid + i * 128;
            int row = f >> 2, c = f & 3;
            cp16(st + swz(row * 64 + c * 16),
                 Ach + (long)(bm + row) * DICT + kof + c * 8);
        }
#pragma unroll
        for (int i = 0; i < 4; ++i) {
            int f = tid + i * 128;
            int row = f >> 2, c = f & 3;
            cp16(st + A_BYTES + swz(row * 64 + c * 16),
                 Bch + (long)(bn + row) * DICT + kof + c * 8);
        }
    };

    const int NK = DICT / 32;
#pragma unroll
    for (int s = 0; s < NSTAGE - 1; ++s) { load_chunk(s, s); CP_COMMIT(); }

    const int aRow = (lm & 1) * 8 + lr;
    const int aChk = lm >> 1;
    const int bNt  = lm >> 1;
    const int bChk = lm & 1;

#pragma unroll 1
    for (int ck = 0; ck < NK; ++ck) {
        CP_WAIT(2);
        __syncthreads();
        const int cn = ck + NSTAGE - 1;
        if (cn < NK) load_chunk(cn, cn & (NSTAGE - 1));
        CP_COMMIT();

        const uint32_t st = sb + (ck & (NSTAGE - 1)) * STAGE_BYTES;
#pragma unroll
        for (int ks = 0; ks < 2; ++ks) {
            uint32_t a[2][4], b[8][2];
#pragma unroll
            for (int mi = 0; mi < 2; ++mi) {
                int row = wm * 32 + mi * 16 + aRow;
                int ch  = ks * 2 + aChk;
                ldmx4(a[mi], st + swz(row * 64 + ch * 16));
            }
#pragma unroll
            for (int p = 0; p < 4; ++p) {
                int nt  = p * 2 + bNt;
                int ch  = ks * 2 + bChk;
                int row = wn * 64 + nt * 8 + lr;
                uint32_t r[4];
                ldmx4(r, st + A_BYTES + swz(row * 64 + ch * 16));
                b[p * 2][0] = r[0]; b[p * 2][1] = r[1];
                b[p * 2 + 1][0] = r[2]; b[p * 2 + 1][1] = r[3];
            }
#pragma unroll
            for (int mi = 0; mi < 2; ++mi)
#pragma unroll
                for (int ni = 0; ni < 8; ++ni)
                    mma_f16(acc[mi][ni], a[mi], b[ni]);
        }
    }

    const int qr = lane >> 2;
    const int qc = lane & 3;
    const float* Afc = Af   + (long)cz * slab;
    const float* Ych = Yp   + (long)cz * slab;
    const float* Och = Xold + (long)cz * slab;
    float*       Mch = Xm32 + (long)cz * slab;
    __half*      Hch = XmH  + (long)cz * slab;
    float*       Cch = Cn   + (long)cz * slab;

#pragma unroll
    for (int mi = 0; mi < 2; ++mi) {
        const int r0 = bm + wm * 32 + mi * 16 + qr;
#pragma unroll
        for (int ni = 0; ni < 8; ++ni) {
            const int col = bn + wn * 64 + ni * 8 + qc * 2;
            const long off0 = (long)r0 * DICT + col;
            const long off1 = off0 + 8L * DICT;
            const float2 xt0 = *(const float2*)(Afc + off0);
            const float2 xt1 = *(const float2*)(Afc + off1);
            const float2 y0  = *(const float2*)(Ych + off0);
            const float2 y1  = *(const float2*)(Ych + off1);
            float v00 = xt0.x + TAUV * (y0.x - acc[mi][ni][0]);
            float v01 = xt0.y + TAUV * (y0.y - acc[mi][ni][1]);
            float v10 = xt1.x + TAUV * (y1.x - acc[mi][ni][2]);
            float v11 = xt1.y + TAUV * (y1.y - acc[mi][ni][3]);
            float ss0 = fmaf(v00, v00, v01 * v01);
            float ss1 = fmaf(v10, v10, v11 * v11);
            ss0 += __shfl_xor_sync(0xffffffffu, ss0, 1);
            ss1 += __shfl_xor_sync(0xffffffffu, ss1, 1);
            ss0 += __shfl_xor_sync(0xffffffffu, ss0, 2);
            ss1 += __shfl_xor_sync(0xffffffffu, ss1, 2);
            const float sc0 = fmaxf(1.f - (LAMV * TAUV) * rsqrtf(ss0), 0.f);
            const float sc1 = fmaxf(1.f - (LAMV * TAUV) * rsqrtf(ss1), 0.f);
            const float2 xo0 = *(const float2*)(Och + off0);
            const float2 xo1 = *(const float2*)(Och + off1);
            float xn00 = sc0 * fmaxf(v00, 0.f);
            float xn01 = sc0 * fmaxf(v01, 0.f);
            float xn10 = sc1 * fmaxf(v10, 0.f);
            float xn11 = sc1 * fmaxf(v11, 0.f);
            float xm00 = xn00 + beta * (xn00 - xo0.x);
            float xm01 = xn01 + beta * (xn01 - xo0.y);
            float xm10 = xn10 + beta * (xn10 - xo1.x);
            float xm11 = xn11 + beta * (xn11 - xo1.y);
            *(float2*)(Cch + off0) = make_float2(xn00, xn01);
            *(float2*)(Cch + off1) = make_float2(xn10, xn11);
            *(float2*)(Mch + off0) = make_float2(xm00, xm01);
            *(float2*)(Mch + off1) = make_float2(xm10, xm11);
            *(__half2*)(Hch + off0) = __floats2half2_rn(xm00, xm01);
            *(__half2*)(Hch + off1) = __floats2half2_rn(xm10, xm11);
        }
    }
}

// fp32 -> fp16 bulk convert (4 floats/thread)
__global__ void cvt_f2h(const float4* __restrict__ in, __half2* __restrict__ out, int n4)
{
    int i = blockIdx.x * 256 + threadIdx.x;
    if (i < n4) {
        float4 v = in[i];
        out[2 * i]     = __floats2half2_rn(v.x, v.y);
        out[2 * i + 1] = __floats2half2_rn(v.z, v.w);
    }
}

// W [C,D,N] fp32 -> Wt [C,N,D] fp16 (decoder B operand)
__global__ void transpose_wh(const float* __restrict__ W, __half* __restrict__ Wt)
{
    __shared__ float tile[32][33];
    const int cz = blockIdx.z;
    const int d0 = blockIdx.x * 32;
    const int n0 = blockIdx.y * 32;
    const float* Wc  = W  + (long)cz * DICT * NIN;
    __half*      Wtc = Wt + (long)cz * NIN * DICT;
    const int tx = threadIdx.x, ty = threadIdx.y;
#pragma unroll
    for (int r = 0; r < 32; r += 8)
        tile[ty + r][tx] = Wc[(long)(d0 + ty + r) * NIN + n0 + tx];
    __syncthreads();
#pragma unroll
    for (int r = 0; r < 32; r += 8)
        Wtc[(long)(n0 + ty + r) * DICT + d0 + tx] = __float2half(tile[tx][ty + r]);
}

extern "C" void kernel_launch(void* const* d_in, const int* in_sizes, int n_in,
                              void* d_out, int out_size)
{
    const float* x;
    const float* W;
    if (in_sizes[0] == BATCH * CH * NIN) { x = (const float*)d_in[0]; W = (const float*)d_in[1]; }
    else                                 { x = (const float*)d_in[1]; W = (const float*)d_in[0]; }

    __half *Gh, *Wh, *Wth, *xh, *zh, *bufh;
    float *G, *Y, *buf;
    cudaGetSymbolAddress((void**)&G,    g_G);
    cudaGetSymbolAddress((void**)&Gh,   g_Gh);
    cudaGetSymbolAddress((void**)&Y,    g_Y);
    cudaGetSymbolAddress((void**)&Wh,   g_Wh);
    cudaGetSymbolAddress((void**)&Wth,  g_Wth);
    cudaGetSymbolAddress((void**)&xh,   g_xh);
    cudaGetSymbolAddress((void**)&zh,   g_zh);
    cudaGetSymbolAddress((void**)&buf,  g_buf);
    cudaGetSymbolAddress((void**)&bufh, g_bufh);
    const long slab = (long)CH * BATCH * DICT;

    cudaFuncSetAttribute(hgemm<0>,   cudaFuncAttributeMaxDynamicSharedMemorySize, SMEM_DYN);
    cudaFuncSetAttribute(hgemm<3>,   cudaFuncAttributeMaxDynamicSharedMemorySize, SMEM_DYN);
    cudaFuncSetAttribute(tgemm_fista, cudaFuncAttributeMaxDynamicSharedMemorySize, SMEM_DYN);
    cudaFuncSetAttribute(hgemm_fista, cudaFuncAttributeMaxDynamicSharedMemorySize, SMEM_DYN);

    float betas[LAYERS];
    float tt = 1.f;
    for (int i = 0; i < LAYERS; ++i) {
        float tn = (1.f + sqrtf(1.f + 4.f * tt * tt)) * 0.5f;
        betas[i] = (tt - 1.f) / tn;
        tt = tn;
    }

    cudaMemsetAsync(buf,  0, (size_t)2 * slab * sizeof(float));
    cudaMemsetAsync(bufh, 0, (size_t)slab * sizeof(__half));

    // Convert W and x to fp16 (11-bit rounding == what tf32 MMA applies anyway)
    {
        int n4 = (CH * DICT * NIN) / 4;
        cvt_f2h<<<(n4 + 255) / 256, 256>>>((const float4*)W, (__half2*)Wh, n4);
    }
    {
        int n4 = (BATCH * CH * NIN) / 4;
        cvt_f2h<<<(n4 + 255) / 256, 256>>>((const float4*)x, (__half2*)xh, n4);
    }

    // Gram: G_c = W_c · W_c^T (fp16 MMA, fp32 acc) -> G fp32 + Gh fp16
    hgemm<3><<<dim3(DICT / BN, DICT / BM, CH), 128, SMEM_DYN>>>(
        Wh, (long)DICT * NIN, NIN,
        Wh, (long)DICT * NIN, NIN,
        G, (long)DICT * DICT, DICT, NIN);

    // Y_c = x_c · W_c^T (fp16 MMA, fp32 out)
    hgemm<0><<<dim3(DICT / BN, BATCH / BM, CH), 128, SMEM_DYN>>>(
        xh, (long)NIN, CH * NIN,
        Wh, (long)DICT * NIN, NIN,
        Y, (long)BATCH * DICT, DICT, NIN);

    transpose_wh<<<dim3(DICT / 32, NIN / 32, CH), dim3(32, 8)>>>(W, Wth);

    // FISTA: iterations 0..21 fp16, 22..29 tf32 cleanup
    for (int i = 0; i < LAYERS; ++i) {
        const int odd = i & 1;
        float*  oldb = buf  + (odd ? 2 : 0) * slab;
        float*  tmpb = buf  + (odd ? 3 : 1) * slab;
        float*  newb = buf  + (odd ? 0 : 2) * slab;
        float*  momb = buf  + (odd ? 1 : 3) * slab;
        __half* tmph = bufh + (odd ? 1 : 0) * slab;
        __half* momh = bufh + (odd ? 0 : 1) * slab;
        if (i < NFP16) {
            hgemm_fista<<<dim3(DICT / BN, BATCH / BM, CH), 128, SMEM_DYN>>>(
                tmph, tmpb, Gh, newb, Y, oldb, momb, momh, betas[i]);
        } else {
            tgemm_fista<<<dim3(DICT / BN, BATCH / BM, CH), 128, SMEM_DYN>>>(
                tmpb, G, newb, Y, oldb, momb, betas[i]);
        }
    }

    float* z = buf;   // x_new after iter 29 (odd) is slab 0

    // Decoder: x_hat_c = z_c · W_c (fp16 MMA) -> d_out [B,C,N] fp32
    {
        int n4 = (int)(slab / 4);
        cvt_f2h<<<(n4 + 255) / 256, 256>>>((const float4*)z, (__half2*)zh, n4);
    }
    hgemm<0><<<dim3(NIN / BN, BATCH / BM, CH), 128, SMEM_DYN>>>(
        zh, (long)BATCH * DICT, DICT,
        Wth, (long)NIN * DICT, DICT,
        (float*)d_out, (long)NIN, CH * NIN, DICT);
}